// round 7
// baseline (speedup 1.0000x reference)
#include <cuda_runtime.h>
#include <cstdint>

#define SEQ    2048
#define BATCH  2
#define DM     1024
#define NH     16
#define DH     64
#define MROWS  (SEQ * BATCH)      // 4096
#define QKV_N  (3 * DM)           // 3072

// Scratch (allocation-free rule: __device__ globals)
__device__ float g_qkv[(size_t)MROWS * QKV_N];   // (t*B+b, 3072)  q|k|v
__device__ float g_av [(size_t)MROWS * DM];      // (t*B+b, 1024)

__device__ __forceinline__ uint32_t f2tf32(float v) {
    uint32_t r;
    asm("cvt.rna.tf32.f32 %0, %1;" : "=r"(r) : "f"(v));
    return r;
}
__device__ __forceinline__ void mma_tf32(float* c, const uint32_t* a, const uint32_t* b) {
    asm volatile(
        "mma.sync.aligned.m16n8k8.row.col.f32.tf32.tf32.f32 "
        "{%0,%1,%2,%3}, {%4,%5,%6,%7}, {%8,%9}, {%0,%1,%2,%3};"
        : "+f"(c[0]), "+f"(c[1]), "+f"(c[2]), "+f"(c[3])
        : "r"(a[0]), "r"(a[1]), "r"(a[2]), "r"(a[3]), "r"(b[0]), "r"(b[1]));
}
__device__ __forceinline__ void split4(const float4 v, uint4& h, uint4& l) {
    h.x = f2tf32(v.x); l.x = f2tf32(v.x - __uint_as_float(h.x));
    h.y = f2tf32(v.y); l.y = f2tf32(v.y - __uint_as_float(h.y));
    h.z = f2tf32(v.z); l.z = f2tf32(v.z - __uint_as_float(h.z));
    h.w = f2tf32(v.w); l.w = f2tf32(v.w - __uint_as_float(h.w));
}

// ===========================================================================
// 3xTF32 warp-MMA GEMM, smem double-buffered (1 barrier / K-chunk).
// C[M,N] = A[M,K] @ B[N,K]^T + bias[N]; CTA 128x128, 8 warps, K-chunks of 32.
// ===========================================================================
#define GS 36
#define TILE_FLOATS (128 * GS)
#define STAGE_FLOATS (4 * TILE_FLOATS)              // Ah,Al,Bh,Bl
#define GEMM_SMEM   (2 * STAGE_FLOATS * 4)          // 147456 B

__global__ __launch_bounds__(256, 1) void gemm_tf32_mma(
    const float* __restrict__ A, const float* __restrict__ Bw,
    const float* __restrict__ bias, float* __restrict__ C,
    int M, int N, int K)
{
    extern __shared__ float smf[];

    const int tid  = threadIdx.x;
    const int wid  = tid >> 5;
    const int lane = tid & 31;
    const int gid  = lane >> 2;
    const int tig  = lane & 3;
    const int mw   = (wid & 1) * 64;
    const int nw   = (wid >> 1) * 32;
    const int row0 = blockIdx.y * 128;
    const int col0 = blockIdx.x * 128;

    float acc[4][4][4];
#pragma unroll
    for (int i = 0; i < 4; i++)
#pragma unroll
        for (int j = 0; j < 4; j++)
#pragma unroll
            for (int e = 0; e < 4; e++) acc[i][j][e] = 0.f;

    const int ldr = tid >> 3;
    const int ldc = (tid & 7) << 2;

    float4 pa[4], pb[4];
    // Prologue: load chunk 0, store to buffer 0.
#pragma unroll
    for (int it = 0; it < 4; it++) {
        const int r = ldr + it * 32;
        pa[it] = *(const float4*)(A  + (size_t)(row0 + r) * K + ldc);
        pb[it] = *(const float4*)(Bw + (size_t)(col0 + r) * K + ldc);
    }
    {
        float* Ah = smf;  float* Al = Ah + TILE_FLOATS;
        float* Bh = Al + TILE_FLOATS; float* Bl = Bh + TILE_FLOATS;
#pragma unroll
        for (int it = 0; it < 4; it++) {
            const int r = ldr + it * 32;
            uint4 h, l;
            split4(pa[it], h, l);
            *(uint4*)(Ah + r * GS + ldc) = h;
            *(uint4*)(Al + r * GS + ldc) = l;
            split4(pb[it], h, l);
            *(uint4*)(Bh + r * GS + ldc) = h;
            *(uint4*)(Bl + r * GS + ldc) = l;
        }
    }
    // Load chunk 1 into regs.
    const int KCH = K >> 5;
    if (KCH > 1) {
#pragma unroll
        for (int it = 0; it < 4; it++) {
            const int r = ldr + it * 32;
            pa[it] = *(const float4*)(A  + (size_t)(row0 + r) * K + 32 + ldc);
            pb[it] = *(const float4*)(Bw + (size_t)(col0 + r) * K + 32 + ldc);
        }
    }
    __syncthreads();

    for (int kt = 0; kt < KCH; kt++) {
        float* cur = smf + (kt & 1) * STAGE_FLOATS;
        float* nxt = smf + ((kt + 1) & 1) * STAGE_FLOATS;

        // Store chunk kt+1 into the other buffer (overlaps this chunk's MMA).
        if (kt + 1 < KCH) {
            float* Ah = nxt;  float* Al = Ah + TILE_FLOATS;
            float* Bh = Al + TILE_FLOATS; float* Bl = Bh + TILE_FLOATS;
#pragma unroll
            for (int it = 0; it < 4; it++) {
                const int r = ldr + it * 32;
                uint4 h, l;
                split4(pa[it], h, l);
                *(uint4*)(Ah + r * GS + ldc) = h;
                *(uint4*)(Al + r * GS + ldc) = l;
                split4(pb[it], h, l);
                *(uint4*)(Bh + r * GS + ldc) = h;
                *(uint4*)(Bl + r * GS + ldc) = l;
            }
        }
        // Issue loads for chunk kt+2 (retire under two MMA blocks).
        if (kt + 2 < KCH) {
            const int k0n = (kt + 2) << 5;
#pragma unroll
            for (int it = 0; it < 4; it++) {
                const int r = ldr + it * 32;
                pa[it] = *(const float4*)(A  + (size_t)(row0 + r) * K + k0n + ldc);
                pb[it] = *(const float4*)(Bw + (size_t)(col0 + r) * K + k0n + ldc);
            }
        }

        // MMA on the current buffer.
        {
            float* Ah = cur;  float* Al = Ah + TILE_FLOATS;
            float* Bh = Al + TILE_FLOATS; float* Bl = Bh + TILE_FLOATS;
#pragma unroll
            for (int ks = 0; ks < 4; ks++) {
                const int kc = ks * 8 + tig;
                uint32_t afh[4][4], afl[4][4], bfh[4][2], bfl[4][2];
#pragma unroll
                for (int i = 0; i < 4; i++) {
                    const int r = mw + i * 16 + gid;
                    afh[i][0] = __float_as_uint(Ah[(r    ) * GS + kc    ]);
                    afh[i][1] = __float_as_uint(Ah[(r + 8) * GS + kc    ]);
                    afh[i][2] = __float_as_uint(Ah[(r    ) * GS + kc + 4]);
                    afh[i][3] = __float_as_uint(Ah[(r + 8) * GS + kc + 4]);
                    afl[i][0] = __float_as_uint(Al[(r    ) * GS + kc    ]);
                    afl[i][1] = __float_as_uint(Al[(r + 8) * GS + kc    ]);
                    afl[i][2] = __float_as_uint(Al[(r    ) * GS + kc + 4]);
                    afl[i][3] = __float_as_uint(Al[(r + 8) * GS + kc + 4]);
                }
#pragma unroll
                for (int j = 0; j < 4; j++) {
                    const int n = nw + j * 8 + gid;
                    bfh[j][0] = __float_as_uint(Bh[n * GS + kc    ]);
                    bfh[j][1] = __float_as_uint(Bh[n * GS + kc + 4]);
                    bfl[j][0] = __float_as_uint(Bl[n * GS + kc    ]);
                    bfl[j][1] = __float_as_uint(Bl[n * GS + kc + 4]);
                }
#pragma unroll
                for (int i = 0; i < 4; i++)
#pragma unroll
                    for (int j = 0; j < 4; j++) {
                        mma_tf32(acc[i][j], afh[i], bfh[j]);
                        mma_tf32(acc[i][j], afh[i], bfl[j]);
                        mma_tf32(acc[i][j], afl[i], bfh[j]);
                    }
            }
        }
        __syncthreads();
    }

#pragma unroll
    for (int i = 0; i < 4; i++) {
        const int r = row0 + mw + i * 16 + gid;
#pragma unroll
        for (int j = 0; j < 4; j++) {
            const int ccol = col0 + nw + j * 8 + tig * 2;
            float2 v0, v1;
            v0.x = acc[i][j][0] + bias[ccol];
            v0.y = acc[i][j][1] + bias[ccol + 1];
            v1.x = acc[i][j][2] + bias[ccol];
            v1.y = acc[i][j][3] + bias[ccol + 1];
            *(float2*)(C + (size_t)r * N + ccol)       = v0;
            *(float2*)(C + (size_t)(r + 8) * N + ccol) = v1;
        }
    }
}

// ===========================================================================
// Tensor-core flash attention (3xTF32, pipelined K/V prefetch) — as R6.
// ===========================================================================
#define AS 68
#define ATT_TILE (64 * AS)
#define ATT_SMEM_BYTES (6 * ATT_TILE * 4)     // 104448 B

__global__ __launch_bounds__(128, 2) void flash_attn_tc(
    const float* __restrict__ qkv, const int* __restrict__ causal_flag,
    float* __restrict__ av)
{
    extern __shared__ float sm[];
    float* Kh = sm;
    float* Kl = Kh + ATT_TILE;
    float* Vh = Kl + ATT_TILE;
    float* Vl = Vh + ATT_TILE;
    float* Ph = Vl + ATT_TILE;
    float* Pl = Ph + ATT_TILE;

    const int tid  = threadIdx.x;
    const int wid  = tid >> 5;
    const int lane = tid & 31;
    const int gid  = lane >> 2;
    const int tig  = lane & 3;
    const int qt   = blockIdx.x;
    const int b    = blockIdx.y >> 4;
    const int h    = blockIdx.y & 15;
    const int is_causal = *causal_flag;

    const int lr  = tid >> 4;
    const int ld4 = (tid & 15) << 2;

    uint32_t qh[8][4], ql[8][4];
    {
        const int r0 = qt * 64 + wid * 16 + gid;
        const float* q0 = qkv + ((size_t)(r0 * BATCH + b)) * QKV_N + h * DH;
        const float* q8 = q0 + (size_t)8 * BATCH * QKV_N;
#pragma unroll
        for (int ks = 0; ks < 8; ks++) {
            const float v0 = q0[ks * 8 + tig];
            const float v1 = q8[ks * 8 + tig];
            const float v2 = q0[ks * 8 + tig + 4];
            const float v3 = q8[ks * 8 + tig + 4];
            qh[ks][0] = f2tf32(v0); ql[ks][0] = f2tf32(v0 - __uint_as_float(qh[ks][0]));
            qh[ks][1] = f2tf32(v1); ql[ks][1] = f2tf32(v1 - __uint_as_float(qh[ks][1]));
            qh[ks][2] = f2tf32(v2); ql[ks][2] = f2tf32(v2 - __uint_as_float(qh[ks][2]));
            qh[ks][3] = f2tf32(v3); ql[ks][3] = f2tf32(v3 - __uint_as_float(qh[ks][3]));
        }
    }

    float4 kreg[8], vreg[8];
#pragma unroll
    for (int it = 0; it < 8; it++) {
        const int r = lr + it * 8;
        const float* base = qkv + ((size_t)((r) * BATCH + b)) * QKV_N + h * DH + ld4;
        kreg[it] = *(const float4*)(base + DM);
        vreg[it] = *(const float4*)(base + 2 * DM);
    }

    float o[8][4];
#pragma unroll
    for (int j = 0; j < 8; j++)
#pragma unroll
        for (int e = 0; e < 4; e++) o[j][e] = 0.f;
    float m0 = -1e30f, m1 = -1e30f, l0 = 0.f, l1 = 0.f;

    const int kt_end = is_causal ? qt : (SEQ / 64 - 1);

    for (int kt = 0; kt <= kt_end; kt++) {
        __syncthreads();
#pragma unroll
        for (int it = 0; it < 8; it++) {
            const int r = lr + it * 8;
            uint4 hh, ll;
            split4(kreg[it], hh, ll);
            *(uint4*)(Kh + r * AS + ld4) = hh;
            *(uint4*)(Kl + r * AS + ld4) = ll;
            split4(vreg[it], hh, ll);
            *(uint4*)(Vh + r * AS + ld4) = hh;
            *(uint4*)(Vl + r * AS + ld4) = ll;
        }
        __syncthreads();

        if (kt < kt_end) {
#pragma unroll
            for (int it = 0; it < 8; it++) {
                const int r = (kt + 1) * 64 + lr + it * 8;
                kreg[it] = *(const float4*)(
                    qkv + ((size_t)(r * BATCH + b)) * QKV_N + h * DH + ld4 + DM);
            }
        }

        float s[8][4];
#pragma unroll
        for (int j = 0; j < 8; j++)
#pragma unroll
            for (int e = 0; e < 4; e++) s[j][e] = 0.f;

#pragma unroll
        for (int ks = 0; ks < 8; ks++) {
            const int kc = ks * 8 + tig;
#pragma unroll
            for (int j = 0; j < 8; j++) {
                const int n = j * 8 + gid;
                uint32_t bh[2], bl[2];
                bh[0] = __float_as_uint(Kh[n * AS + kc    ]);
                bh[1] = __float_as_uint(Kh[n * AS + kc + 4]);
                bl[0] = __float_as_uint(Kl[n * AS + kc    ]);
                bl[1] = __float_as_uint(Kl[n * AS + kc + 4]);
                mma_tf32(s[j], qh[ks], bh);
                mma_tf32(s[j], qh[ks], bl);
                mma_tf32(s[j], ql[ks], bh);
            }
        }

#pragma unroll
        for (int j = 0; j < 8; j++)
#pragma unroll
            for (int e = 0; e < 4; e++) s[j][e] *= 8.0f;

        if (is_causal && kt == qt) {
            const int r0 = wid * 16 + gid;
#pragma unroll
            for (int j = 0; j < 8; j++) {
                const int c = j * 8 + tig * 2;
                if (c     > r0)     s[j][0] = -1e30f;
                if (c + 1 > r0)     s[j][1] = -1e30f;
                if (c     > r0 + 8) s[j][2] = -1e30f;
                if (c + 1 > r0 + 8) s[j][3] = -1e30f;
            }
        }

        float rm0 = -1e30f, rm1 = -1e30f;
#pragma unroll
        for (int j = 0; j < 8; j++) {
            rm0 = fmaxf(rm0, fmaxf(s[j][0], s[j][1]));
            rm1 = fmaxf(rm1, fmaxf(s[j][2], s[j][3]));
        }
        rm0 = fmaxf(rm0, __shfl_xor_sync(0xffffffffu, rm0, 1));
        rm0 = fmaxf(rm0, __shfl_xor_sync(0xffffffffu, rm0, 2));
        rm1 = fmaxf(rm1, __shfl_xor_sync(0xffffffffu, rm1, 1));
        rm1 = fmaxf(rm1, __shfl_xor_sync(0xffffffffu, rm1, 2));

        const float mn0 = fmaxf(m0, rm0);
        const float mn1 = fmaxf(m1, rm1);
        const float corr0 = __expf(m0 - mn0);
        const float corr1 = __expf(m1 - mn1);

        float rs0 = 0.f, rs1 = 0.f;
        const int prow = wid * 16 + gid;
#pragma unroll
        for (int j = 0; j < 8; j++) {
            const float p00 = __expf(s[j][0] - mn0);
            const float p01 = __expf(s[j][1] - mn0);
            const float p10 = __expf(s[j][2] - mn1);
            const float p11 = __expf(s[j][3] - mn1);
            rs0 += p00 + p01;
            rs1 += p10 + p11;
            float2 h2, l2;
            h2.x = __uint_as_float(f2tf32(p00)); l2.x = p00 - h2.x;
            h2.y = __uint_as_float(f2tf32(p01)); l2.y = p01 - h2.y;
            l2.x = __uint_as_float(f2tf32(l2.x));
            l2.y = __uint_as_float(f2tf32(l2.y));
            *(float2*)(Ph + prow * AS + j * 8 + tig * 2) = h2;
            *(float2*)(Pl + prow * AS + j * 8 + tig * 2) = l2;
            h2.x = __uint_as_float(f2tf32(p10)); l2.x = p10 - h2.x;
            h2.y = __uint_as_float(f2tf32(p11)); l2.y = p11 - h2.y;
            l2.x = __uint_as_float(f2tf32(l2.x));
            l2.y = __uint_as_float(f2tf32(l2.y));
            *(float2*)(Ph + (prow + 8) * AS + j * 8 + tig * 2) = h2;
            *(float2*)(Pl + (prow + 8) * AS + j * 8 + tig * 2) = l2;
        }
        rs0 += __shfl_xor_sync(0xffffffffu, rs0, 1);
        rs0 += __shfl_xor_sync(0xffffffffu, rs0, 2);
        rs1 += __shfl_xor_sync(0xffffffffu, rs1, 1);
        rs1 += __shfl_xor_sync(0xffffffffu, rs1, 2);

        l0 = l0 * corr0 + rs0;
        l1 = l1 * corr1 + rs1;
        m0 = mn0;
        m1 = mn1;

#pragma unroll
        for (int j = 0; j < 8; j++) {
            o[j][0] *= corr0; o[j][1] *= corr0;
            o[j][2] *= corr1; o[j][3] *= corr1;
        }

        if (kt < kt_end) {
#pragma unroll
            for (int it = 0; it < 8; it++) {
                const int r = (kt + 1) * 64 + lr + it * 8;
                vreg[it] = *(const float4*)(
                    qkv + ((size_t)(r * BATCH + b)) * QKV_N + h * DH + ld4 + 2 * DM);
            }
        }

        __syncwarp();

#pragma unroll
        for (int ks = 0; ks < 8; ks++) {
            const int kc = ks * 8 + tig;
            uint32_t ah[4], al[4];
            ah[0] = __float_as_uint(Ph[(prow    ) * AS + kc    ]);
            ah[1] = __float_as_uint(Ph[(prow + 8) * AS + kc    ]);
            ah[2] = __float_as_uint(Ph[(prow    ) * AS + kc + 4]);
            ah[3] = __float_as_uint(Ph[(prow + 8) * AS + kc + 4]);
            al[0] = __float_as_uint(Pl[(prow    ) * AS + kc    ]);
            al[1] = __float_as_uint(Pl[(prow + 8) * AS + kc    ]);
            al[2] = __float_as_uint(Pl[(prow    ) * AS + kc + 4]);
            al[3] = __float_as_uint(Pl[(prow + 8) * AS + kc + 4]);
#pragma unroll
            for (int j = 0; j < 8; j++) {
                const int n = j * 8 + gid;
                uint32_t bh[2], bl[2];
                bh[0] = __float_as_uint(Vh[(kc    ) * AS + n]);
                bh[1] = __float_as_uint(Vh[(kc + 4) * AS + n]);
                bl[0] = __float_as_uint(Vl[(kc    ) * AS + n]);
                bl[1] = __float_as_uint(Vl[(kc + 4) * AS + n]);
                mma_tf32(o[j], ah, bh);
                mma_tf32(o[j], ah, bl);
                mma_tf32(o[j], al, bh);
            }
        }
    }

    const float inv0 = 1.0f / l0;
    const float inv1 = 1.0f / l1;
    const int r0 = qt * 64 + wid * 16 + gid;
    float* dst0 = av + ((size_t)(r0 * BATCH + b)) * DM + h * DH;
    float* dst8 = dst0 + (size_t)8 * BATCH * DM;
#pragma unroll
    for (int j = 0; j < 8; j++) {
        float2 v;
        v.x = o[j][0] * inv0; v.y = o[j][1] * inv0;
        *(float2*)(dst0 + j * 8 + tig * 2) = v;
        v.x = o[j][2] * inv1; v.y = o[j][3] * inv1;
        *(float2*)(dst8 + j * 8 + tig * 2) = v;
    }
}

// ---------------------------------------------------------------------------
extern "C" void kernel_launch(void* const* d_in, const int* in_sizes, int n_in,
                              void* d_out, int out_size)
{
    const float* x         = (const float*)d_in[0];
    const float* qkv_w     = (const float*)d_in[1];
    const float* qkv_b     = (const float*)d_in[2];
    const float* out_w     = (const float*)d_in[3];
    const float* out_b     = (const float*)d_in[4];
    const int*   is_causal = (const int*)d_in[5];
    float*       out       = (float*)d_out;

    void* qkv_ptr = nullptr;
    void* av_ptr  = nullptr;
    cudaGetSymbolAddress(&qkv_ptr, g_qkv);
    cudaGetSymbolAddress(&av_ptr,  g_av);

    cudaFuncSetAttribute(gemm_tf32_mma,
                         cudaFuncAttributeMaxDynamicSharedMemorySize, GEMM_SMEM);
    cudaFuncSetAttribute(flash_attn_tc,
                         cudaFuncAttributeMaxDynamicSharedMemorySize, ATT_SMEM_BYTES);

    // QKV projection: (4096,1024) @ (3072,1024)^T -> (4096,3072)
    {
        dim3 grid(QKV_N / 128, MROWS / 128);
        gemm_tf32_mma<<<grid, 256, GEMM_SMEM>>>(x, qkv_w, qkv_b, (float*)qkv_ptr,
                                                MROWS, QKV_N, DM);
    }

    // Attention (tensor-core flash, pipelined)
    {
        dim3 grid(SEQ / 64, BATCH * NH);
        flash_attn_tc<<<grid, 128, ATT_SMEM_BYTES>>>(
            (const float*)qkv_ptr, is_causal, (float*)av_ptr);
    }

    // Output projection: (4096,1024) @ (1024,1024)^T -> (4096,1024)
    {
        dim3 grid(DM / 128, MROWS / 128);
        gemm_tf32_mma<<<grid, 256, GEMM_SMEM>>>((const float*)av_ptr, out_w, out_b, out,
                                                MROWS, DM, DM);
    }
}

// round 10
// speedup vs baseline: 1.8340x; 1.8340x over previous
#include <cuda_runtime.h>
#include <cstdint>

#define SEQ    2048
#define BATCH  2
#define DM     1024
#define NH     16
#define DH     64
#define MROWS  (SEQ * BATCH)      // 4096
#define QKV_N  (3 * DM)           // 3072

// Scratch (allocation-free rule: __device__ globals)
__device__ float g_qkv[(size_t)MROWS * QKV_N];   // (t*B+b, 3072)  q|k|v
__device__ float g_av [(size_t)MROWS * DM];      // (t*B+b, 1024)

// ---------------------------------------------------------------------------
// bf16x2 helpers. split2bf: h = {lo: bf16(x), hi: bf16(y)}, l = residuals.
// ---------------------------------------------------------------------------
__device__ __forceinline__ void split2bf(float x, float y, uint32_t& h, uint32_t& l) {
    asm("cvt.rn.bf16x2.f32 %0, %1, %2;" : "=r"(h) : "f"(y), "f"(x));
    const float hx = __uint_as_float(h << 16);
    const float hy = __uint_as_float(h & 0xFFFF0000u);
    asm("cvt.rn.bf16x2.f32 %0, %1, %2;" : "=r"(l) : "f"(y - hy), "f"(x - hx));
}
__device__ __forceinline__ void mma_bf16(float* c, const uint32_t* a, const uint32_t* b) {
    asm volatile(
        "mma.sync.aligned.m16n8k16.row.col.f32.bf16.bf16.f32 "
        "{%0,%1,%2,%3}, {%4,%5,%6,%7}, {%8,%9}, {%0,%1,%2,%3};"
        : "+f"(c[0]), "+f"(c[1]), "+f"(c[2]), "+f"(c[3])
        : "r"(a[0]), "r"(a[1]), "r"(a[2]), "r"(a[3]), "r"(b[0]), "r"(b[1]));
}

// ===========================================================================
// bf16x2 (3-product) warp-MMA GEMM: C = A @ B^T + bias.
// CTA 128x128, 8 warps (64x32 each), K-chunks of 32 (= 2 x k16 MMA steps).
// Packed tiles: 128 rows x PS uint32 (2 bf16 per uint32 along k).
// ===========================================================================
#define PS 20
#define PTILE (128 * PS)
#define PSTAGE (4 * PTILE)                    // A0,A1,B0,B1
#define GEMM_SMEM (2 * PSTAGE * 4)            // 81920 B (double buffered)

__global__ __launch_bounds__(256, 1) void gemm_bf16x2(
    const float* __restrict__ A, const float* __restrict__ Bw,
    const float* __restrict__ bias, float* __restrict__ C,
    int M, int N, int K)
{
    extern __shared__ uint32_t smu[];

    const int tid  = threadIdx.x;
    const int wid  = tid >> 5;
    const int lane = tid & 31;
    const int gid  = lane >> 2;
    const int tig  = lane & 3;
    const int mw   = (wid & 1) * 64;
    const int nw   = (wid >> 1) * 32;
    const int row0 = blockIdx.y * 128;
    const int col0 = blockIdx.x * 128;

    float acc[4][4][4];
#pragma unroll
    for (int i = 0; i < 4; i++)
#pragma unroll
        for (int j = 0; j < 4; j++)
#pragma unroll
            for (int e = 0; e < 4; e++) acc[i][j][e] = 0.f;

    const int ldr = tid >> 3;           // 0..31 row slice
    const int ldc = (tid & 7) << 2;     // float col 0..28
    const int lcp = (tid & 7) << 1;     // packed col 0..14

    float4 pa[4], pb[4];
#pragma unroll
    for (int it = 0; it < 4; it++) {
        const int r = ldr + it * 32;
        pa[it] = *(const float4*)(A  + (size_t)(row0 + r) * K + ldc);
        pb[it] = *(const float4*)(Bw + (size_t)(col0 + r) * K + ldc);
    }
    {
        uint32_t* A0 = smu;            uint32_t* A1 = A0 + PTILE;
        uint32_t* B0 = A1 + PTILE;     uint32_t* B1 = B0 + PTILE;
#pragma unroll
        for (int it = 0; it < 4; it++) {
            const int r = ldr + it * 32;
            uint32_t h0, l0, h1, l1;
            split2bf(pa[it].x, pa[it].y, h0, l0);
            split2bf(pa[it].z, pa[it].w, h1, l1);
            *(uint2*)(A0 + r * PS + lcp) = make_uint2(h0, h1);
            *(uint2*)(A1 + r * PS + lcp) = make_uint2(l0, l1);
            split2bf(pb[it].x, pb[it].y, h0, l0);
            split2bf(pb[it].z, pb[it].w, h1, l1);
            *(uint2*)(B0 + r * PS + lcp) = make_uint2(h0, h1);
            *(uint2*)(B1 + r * PS + lcp) = make_uint2(l0, l1);
        }
    }
    const int KCH = K >> 5;
    if (KCH > 1) {
#pragma unroll
        for (int it = 0; it < 4; it++) {
            const int r = ldr + it * 32;
            pa[it] = *(const float4*)(A  + (size_t)(row0 + r) * K + 32 + ldc);
            pb[it] = *(const float4*)(Bw + (size_t)(col0 + r) * K + 32 + ldc);
        }
    }
    __syncthreads();

    for (int kt = 0; kt < KCH; kt++) {
        uint32_t* cur = smu + (kt & 1) * PSTAGE;
        uint32_t* nxt = smu + ((kt + 1) & 1) * PSTAGE;

        if (kt + 1 < KCH) {
            uint32_t* A0 = nxt;        uint32_t* A1 = A0 + PTILE;
            uint32_t* B0 = A1 + PTILE; uint32_t* B1 = B0 + PTILE;
#pragma unroll
            for (int it = 0; it < 4; it++) {
                const int r = ldr + it * 32;
                uint32_t h0, l0, h1, l1;
                split2bf(pa[it].x, pa[it].y, h0, l0);
                split2bf(pa[it].z, pa[it].w, h1, l1);
                *(uint2*)(A0 + r * PS + lcp) = make_uint2(h0, h1);
                *(uint2*)(A1 + r * PS + lcp) = make_uint2(l0, l1);
                split2bf(pb[it].x, pb[it].y, h0, l0);
                split2bf(pb[it].z, pb[it].w, h1, l1);
                *(uint2*)(B0 + r * PS + lcp) = make_uint2(h0, h1);
                *(uint2*)(B1 + r * PS + lcp) = make_uint2(l0, l1);
            }
        }
        if (kt + 2 < KCH) {
            const int k0n = (kt + 2) << 5;
#pragma unroll
            for (int it = 0; it < 4; it++) {
                const int r = ldr + it * 32;
                pa[it] = *(const float4*)(A  + (size_t)(row0 + r) * K + k0n + ldc);
                pb[it] = *(const float4*)(Bw + (size_t)(col0 + r) * K + k0n + ldc);
            }
        }

        {
            uint32_t* A0 = cur;        uint32_t* A1 = A0 + PTILE;
            uint32_t* B0 = A1 + PTILE; uint32_t* B1 = B0 + PTILE;
#pragma unroll
            for (int ks = 0; ks < 2; ks++) {
                const int c0 = ks * 8 + tig;
                const int c1 = c0 + 4;
                uint32_t afh[4][4], afl[4][4], bfh[4][2], bfl[4][2];
#pragma unroll
                for (int i = 0; i < 4; i++) {
                    const int r = mw + i * 16 + gid;
                    afh[i][0] = A0[(r    ) * PS + c0];
                    afh[i][1] = A0[(r + 8) * PS + c0];
                    afh[i][2] = A0[(r    ) * PS + c1];
                    afh[i][3] = A0[(r + 8) * PS + c1];
                    afl[i][0] = A1[(r    ) * PS + c0];
                    afl[i][1] = A1[(r + 8) * PS + c0];
                    afl[i][2] = A1[(r    ) * PS + c1];
                    afl[i][3] = A1[(r + 8) * PS + c1];
                }
#pragma unroll
                for (int j = 0; j < 4; j++) {
                    const int n = nw + j * 8 + gid;
                    bfh[j][0] = B0[n * PS + c0];
                    bfh[j][1] = B0[n * PS + c1];
                    bfl[j][0] = B1[n * PS + c0];
                    bfl[j][1] = B1[n * PS + c1];
                }
#pragma unroll
                for (int i = 0; i < 4; i++)
#pragma unroll
                    for (int j = 0; j < 4; j++) {
                        mma_bf16(acc[i][j], afh[i], bfh[j]);
                        mma_bf16(acc[i][j], afh[i], bfl[j]);
                        mma_bf16(acc[i][j], afl[i], bfh[j]);
                    }
            }
        }
        __syncthreads();
    }

#pragma unroll
    for (int i = 0; i < 4; i++) {
        const int r = row0 + mw + i * 16 + gid;
#pragma unroll
        for (int j = 0; j < 4; j++) {
            const int ccol = col0 + nw + j * 8 + tig * 2;
            float2 v0, v1;
            v0.x = acc[i][j][0] + bias[ccol];
            v0.y = acc[i][j][1] + bias[ccol + 1];
            v1.x = acc[i][j][2] + bias[ccol];
            v1.y = acc[i][j][3] + bias[ccol + 1];
            *(float2*)(C + (size_t)r * N + ccol)       = v0;
            *(float2*)(C + (size_t)(r + 8) * N + ccol) = v1;
        }
    }
}

// ===========================================================================
// bf16x2 tensor-core flash attention.
// Block = 128 threads / 4 warps; one (64-row q tile, b, h).
// K,P tiles: 64 x KS_ uint32 (packed along d / s). V: 32 x VS_ (packed along s).
// ===========================================================================
#define KS_ 36
#define VS_ 72
#define K_TILE (64 * KS_)     // 2304 u32
#define V_TILE (32 * VS_)     // 2304 u32
#define ATT_SMEM_BYTES ((4 * K_TILE + 2 * V_TILE) * 4)   // 55296 B

__global__ __launch_bounds__(128, 2) void flash_attn_tc(
    const float* __restrict__ qkv, const int* __restrict__ causal_flag,
    float* __restrict__ av)
{
    extern __shared__ uint32_t smu[];
    uint32_t* K0 = smu;
    uint32_t* K1 = K0 + K_TILE;
    uint32_t* P0 = K1 + K_TILE;
    uint32_t* P1 = P0 + K_TILE;
    uint32_t* V0 = P1 + K_TILE;
    uint32_t* V1 = V0 + V_TILE;

    const int tid  = threadIdx.x;
    const int wid  = tid >> 5;
    const int lane = tid & 31;
    const int gid  = lane >> 2;
    const int tig  = lane & 3;
    const int qt   = blockIdx.x;
    const int b    = blockIdx.y >> 4;
    const int h    = blockIdx.y & 15;
    const int is_causal = *causal_flag;

    // K loader slots
    const int klr = tid >> 4;            // base row 0..7
    const int kd4 = (tid & 15) << 2;     // float col
    const int kcp = (tid & 15) << 1;     // packed col
    // V loader slots
    const int vsp = tid >> 5;            // base packed row 0..3
    const int vd2 = (lane) << 1;         // uint32 col 0..62

    // ---- Q fragments (bf16 hi/lo, packed) ----
    uint32_t qp0[4][4], qp1[4][4];
    {
        const int r0 = qt * 64 + wid * 16 + gid;
        const float* q0 = qkv + ((size_t)(r0 * BATCH + b)) * QKV_N + h * DH;
        const float* q8 = q0 + (size_t)8 * BATCH * QKV_N;
#pragma unroll
        for (int ks = 0; ks < 4; ks++) {
            const float2 qa = *(const float2*)(q0 + ks * 16 + tig * 2);
            const float2 qb = *(const float2*)(q8 + ks * 16 + tig * 2);
            const float2 qc = *(const float2*)(q0 + ks * 16 + tig * 2 + 8);
            const float2 qd = *(const float2*)(q8 + ks * 16 + tig * 2 + 8);
            split2bf(qa.x, qa.y, qp0[ks][0], qp1[ks][0]);
            split2bf(qb.x, qb.y, qp0[ks][1], qp1[ks][1]);
            split2bf(qc.x, qc.y, qp0[ks][2], qp1[ks][2]);
            split2bf(qd.x, qd.y, qp0[ks][3], qp1[ks][3]);
        }
    }

    // Prologue: prefetch K and V for kt = 0.
    float4 kreg[8];
    float2 vra[8], vrb[8];
#pragma unroll
    for (int it = 0; it < 8; it++) {
        const int kr = klr + it * 8;
        kreg[it] = *(const float4*)(
            qkv + ((size_t)(kr * BATCH + b)) * QKV_N + h * DH + kd4 + DM);
        const int sp = vsp + it * 4;
        const float* vb0 =
            qkv + ((size_t)((2 * sp) * BATCH + b)) * QKV_N + h * DH + vd2 + 2 * DM;
        vra[it] = *(const float2*)(vb0);
        vrb[it] = *(const float2*)(vb0 + (size_t)BATCH * QKV_N);
    }

    float o[8][4];
#pragma unroll
    for (int j = 0; j < 8; j++)
#pragma unroll
        for (int e = 0; e < 4; e++) o[j][e] = 0.f;
    float m0 = -1e30f, m1 = -1e30f, l0 = 0.f, l1 = 0.f;

    const int kt_end = is_causal ? qt : (SEQ / 64 - 1);

    for (int kt = 0; kt <= kt_end; kt++) {
        __syncthreads();
        // ---- store prefetched K (packed along d) and V (packed along s) ----
#pragma unroll
        for (int it = 0; it < 8; it++) {
            const int kr = klr + it * 8;
            uint32_t h0, l0_, h1, l1_;
            split2bf(kreg[it].x, kreg[it].y, h0, l0_);
            split2bf(kreg[it].z, kreg[it].w, h1, l1_);
            *(uint2*)(K0 + kr * KS_ + kcp) = make_uint2(h0, h1);
            *(uint2*)(K1 + kr * KS_ + kcp) = make_uint2(l0_, l1_);
            const int sp = vsp + it * 4;
            split2bf(vra[it].x, vrb[it].x, h0, l0_);
            split2bf(vra[it].y, vrb[it].y, h1, l1_);
            *(uint2*)(V0 + sp * VS_ + vd2) = make_uint2(h0, h1);
            *(uint2*)(V1 + sp * VS_ + vd2) = make_uint2(l0_, l1_);
        }
        __syncthreads();

        // Prefetch next K tile (retires under QK MMAs).
        if (kt < kt_end) {
#pragma unroll
            for (int it = 0; it < 8; it++) {
                const int kr = (kt + 1) * 64 + klr + it * 8;
                kreg[it] = *(const float4*)(
                    qkv + ((size_t)(kr * BATCH + b)) * QKV_N + h * DH + kd4 + DM);
            }
        }

        // ---- S = Q K^T (3-product bf16x2) ----
        float s[8][4];
#pragma unroll
        for (int j = 0; j < 8; j++)
#pragma unroll
            for (int e = 0; e < 4; e++) s[j][e] = 0.f;

#pragma unroll
        for (int ks = 0; ks < 4; ks++) {
            const int c0 = ks * 8 + tig;
            const int c1 = c0 + 4;
#pragma unroll
            for (int j = 0; j < 8; j++) {
                const int n = j * 8 + gid;
                uint32_t bh[2], bl[2];
                bh[0] = K0[n * KS_ + c0];
                bh[1] = K0[n * KS_ + c1];
                bl[0] = K1[n * KS_ + c0];
                bl[1] = K1[n * KS_ + c1];
                mma_bf16(s[j], qp0[ks], bh);
                mma_bf16(s[j], qp0[ks], bl);
                mma_bf16(s[j], qp1[ks], bh);
            }
        }

        // ---- scale x8, causal mask ----
#pragma unroll
        for (int j = 0; j < 8; j++)
#pragma unroll
            for (int e = 0; e < 4; e++) s[j][e] *= 8.0f;

        if (is_causal && kt == qt) {
            const int r0 = wid * 16 + gid;
#pragma unroll
            for (int j = 0; j < 8; j++) {
                const int c = j * 8 + tig * 2;
                if (c     > r0)     s[j][0] = -1e30f;
                if (c + 1 > r0)     s[j][1] = -1e30f;
                if (c     > r0 + 8) s[j][2] = -1e30f;
                if (c + 1 > r0 + 8) s[j][3] = -1e30f;
            }
        }

        // ---- online softmax ----
        float rm0 = -1e30f, rm1 = -1e30f;
#pragma unroll
        for (int j = 0; j < 8; j++) {
            rm0 = fmaxf(rm0, fmaxf(s[j][0], s[j][1]));
            rm1 = fmaxf(rm1, fmaxf(s[j][2], s[j][3]));
        }
        rm0 = fmaxf(rm0, __shfl_xor_sync(0xffffffffu, rm0, 1));
        rm0 = fmaxf(rm0, __shfl_xor_sync(0xffffffffu, rm0, 2));
        rm1 = fmaxf(rm1, __shfl_xor_sync(0xffffffffu, rm1, 1));
        rm1 = fmaxf(rm1, __shfl_xor_sync(0xffffffffu, rm1, 2));

        const float mn0 = fmaxf(m0, rm0);
        const float mn1 = fmaxf(m1, rm1);
        const float corr0 = __expf(m0 - mn0);
        const float corr1 = __expf(m1 - mn1);

        float rs0 = 0.f, rs1 = 0.f;
        const int prow = wid * 16 + gid;
#pragma unroll
        for (int j = 0; j < 8; j++) {
            const float p00 = __expf(s[j][0] - mn0);
            const float p01 = __expf(s[j][1] - mn0);
            const float p10 = __expf(s[j][2] - mn1);
            const float p11 = __expf(s[j][3] - mn1);
            rs0 += p00 + p01;
            rs1 += p10 + p11;
            uint32_t hh, ll;
            split2bf(p00, p01, hh, ll);
            P0[prow * KS_ + j * 4 + tig] = hh;
            P1[prow * KS_ + j * 4 + tig] = ll;
            split2bf(p10, p11, hh, ll);
            P0[(prow + 8) * KS_ + j * 4 + tig] = hh;
            P1[(prow + 8) * KS_ + j * 4 + tig] = ll;
        }
        rs0 += __shfl_xor_sync(0xffffffffu, rs0, 1);
        rs0 += __shfl_xor_sync(0xffffffffu, rs0, 2);
        rs1 += __shfl_xor_sync(0xffffffffu, rs1, 1);
        rs1 += __shfl_xor_sync(0xffffffffu, rs1, 2);

        l0 = l0 * corr0 + rs0;
        l1 = l1 * corr1 + rs1;
        m0 = mn0;
        m1 = mn1;

#pragma unroll
        for (int j = 0; j < 8; j++) {
            o[j][0] *= corr0; o[j][1] *= corr0;
            o[j][2] *= corr1; o[j][3] *= corr1;
        }

        // Prefetch next V tile (retires under PV MMAs).
        if (kt < kt_end) {
#pragma unroll
            for (int it = 0; it < 8; it++) {
                const int sp = vsp + it * 4;
                const float* vb0 = qkv +
                    ((size_t)(((kt + 1) * 64 + 2 * sp) * BATCH + b)) * QKV_N +
                    h * DH + vd2 + 2 * DM;
                vra[it] = *(const float2*)(vb0);
                vrb[it] = *(const float2*)(vb0 + (size_t)BATCH * QKV_N);
            }
        }

        __syncwarp();   // P rows for this warp written only by this warp

        // ---- O += P @ V (3-product bf16x2) ----
#pragma unroll
        for (int ks = 0; ks < 4; ks++) {
            const int c0 = ks * 8 + tig;
            const int c1 = c0 + 4;
            uint32_t ah[4], al[4];
            ah[0] = P0[(prow    ) * KS_ + c0];
            ah[1] = P0[(prow + 8) * KS_ + c0];
            ah[2] = P0[(prow    ) * KS_ + c1];
            ah[3] = P0[(prow + 8) * KS_ + c1];
            al[0] = P1[(prow    ) * KS_ + c0];
            al[1] = P1[(prow + 8) * KS_ + c0];
            al[2] = P1[(prow    ) * KS_ + c1];
            al[3] = P1[(prow + 8) * KS_ + c1];
#pragma unroll
            for (int j = 0; j < 8; j++) {
                const int n = j * 8 + gid;
                uint32_t bh[2], bl[2];
                bh[0] = V0[(c0) * VS_ + n];
                bh[1] = V0[(c1) * VS_ + n];
                bl[0] = V1[(c0) * VS_ + n];
                bl[1] = V1[(c1) * VS_ + n];
                mma_bf16(o[j], ah, bh);
                mma_bf16(o[j], ah, bl);
                mma_bf16(o[j], al, bh);
            }
        }
    }

    // ---- normalize + write av in (t, b, h*64+d) layout ----
    const float inv0 = 1.0f / l0;
    const float inv1 = 1.0f / l1;
    const int r0 = qt * 64 + wid * 16 + gid;
    float* dst0 = av + ((size_t)(r0 * BATCH + b)) * DM + h * DH;
    float* dst8 = dst0 + (size_t)8 * BATCH * DM;
#pragma unroll
    for (int j = 0; j < 8; j++) {
        float2 v;
        v.x = o[j][0] * inv0; v.y = o[j][1] * inv0;
        *(float2*)(dst0 + j * 8 + tig * 2) = v;
        v.x = o[j][2] * inv1; v.y = o[j][3] * inv1;
        *(float2*)(dst8 + j * 8 + tig * 2) = v;
    }
}

// ---------------------------------------------------------------------------
extern "C" void kernel_launch(void* const* d_in, const int* in_sizes, int n_in,
                              void* d_out, int out_size)
{
    const float* x         = (const float*)d_in[0];
    const float* qkv_w     = (const float*)d_in[1];
    const float* qkv_b     = (const float*)d_in[2];
    const float* out_w     = (const float*)d_in[3];
    const float* out_b     = (const float*)d_in[4];
    const int*   is_causal = (const int*)d_in[5];
    float*       out       = (float*)d_out;

    void* qkv_ptr = nullptr;
    void* av_ptr  = nullptr;
    cudaGetSymbolAddress(&qkv_ptr, g_qkv);
    cudaGetSymbolAddress(&av_ptr,  g_av);

    cudaFuncSetAttribute(gemm_bf16x2,
                         cudaFuncAttributeMaxDynamicSharedMemorySize, GEMM_SMEM);
    cudaFuncSetAttribute(flash_attn_tc,
                         cudaFuncAttributeMaxDynamicSharedMemorySize, ATT_SMEM_BYTES);

    // QKV projection: (4096,1024) @ (3072,1024)^T -> (4096,3072)
    {
        dim3 grid(QKV_N / 128, MROWS / 128);
        gemm_bf16x2<<<grid, 256, GEMM_SMEM>>>(x, qkv_w, qkv_b, (float*)qkv_ptr,
                                              MROWS, QKV_N, DM);
    }

    // Attention (bf16x2 tensor-core flash)
    {
        dim3 grid(SEQ / 64, BATCH * NH);
        flash_attn_tc<<<grid, 128, ATT_SMEM_BYTES>>>(
            (const float*)qkv_ptr, is_causal, (float*)av_ptr);
    }

    // Output projection: (4096,1024) @ (1024,1024)^T -> (4096,1024)
    {
        dim3 grid(DM / 128, MROWS / 128);
        gemm_bf16x2<<<grid, 256, GEMM_SMEM>>>((const float*)av_ptr, out_w, out_b, out,
                                              MROWS, DM, DM);
    }
}

// round 11
// speedup vs baseline: 1.9101x; 1.0415x over previous
#include <cuda_runtime.h>
#include <cstdint>

#define SEQ    2048
#define BATCH  2
#define DM     1024
#define NH     16
#define DH     64
#define MROWS  (SEQ * BATCH)      // 4096
#define QKV_N  (3 * DM)           // 3072

// Scratch (allocation-free rule: __device__ globals)
__device__ float g_qkv[(size_t)MROWS * QKV_N];   // (t*B+b, 3072)  q|k|v
__device__ float g_av [(size_t)MROWS * DM];      // (t*B+b, 1024)

// ---------------------------------------------------------------------------
// bf16x2 helpers
// ---------------------------------------------------------------------------
__device__ __forceinline__ void split2bf(float x, float y, uint32_t& h, uint32_t& l) {
    asm("cvt.rn.bf16x2.f32 %0, %1, %2;" : "=r"(h) : "f"(y), "f"(x));
    const float hx = __uint_as_float(h << 16);
    const float hy = __uint_as_float(h & 0xFFFF0000u);
    asm("cvt.rn.bf16x2.f32 %0, %1, %2;" : "=r"(l) : "f"(y - hy), "f"(x - hx));
}
__device__ __forceinline__ void mma_bf16(float* c, const uint32_t* a, const uint32_t* b) {
    asm volatile(
        "mma.sync.aligned.m16n8k16.row.col.f32.bf16.bf16.f32 "
        "{%0,%1,%2,%3}, {%4,%5,%6,%7}, {%8,%9}, {%0,%1,%2,%3};"
        : "+f"(c[0]), "+f"(c[1]), "+f"(c[2]), "+f"(c[3])
        : "r"(a[0]), "r"(a[1]), "r"(a[2]), "r"(a[3]), "r"(b[0]), "r"(b[1]));
}
__device__ __forceinline__ void ldsm4(uint32_t* r, uint32_t saddr) {
    asm volatile("ldmatrix.sync.aligned.m8n8.x4.shared.b16 {%0,%1,%2,%3}, [%4];"
                 : "=r"(r[0]), "=r"(r[1]), "=r"(r[2]), "=r"(r[3]) : "r"(saddr));
}

// ===========================================================================
// bf16x2 (3-product) warp-MMA GEMM with ldmatrix fragment loads.
// CTA 128x128, 8 warps (64x32 each), K-chunks of 32 (= 2 x k16 MMA steps).
// Packed tiles: 128 rows x PS uint32 (2 bf16 per uint32 along k).
// ===========================================================================
#define PS 20
#define PTILE (128 * PS)
#define PSTAGE (4 * PTILE)                    // A0,A1,B0,B1
#define GEMM_SMEM (2 * PSTAGE * 4)            // 81920 B (double buffered)

__global__ __launch_bounds__(256, 1) void gemm_bf16x2(
    const float* __restrict__ A, const float* __restrict__ Bw,
    const float* __restrict__ bias, float* __restrict__ C,
    int M, int N, int K)
{
    extern __shared__ uint32_t smu[];
    const uint32_t smem_base = (uint32_t)__cvta_generic_to_shared(smu);

    const int tid  = threadIdx.x;
    const int wid  = tid >> 5;
    const int lane = tid & 31;
    const int gid  = lane >> 2;
    const int tig  = lane & 3;
    const int mw   = (wid & 1) * 64;
    const int nw   = (wid >> 1) * 32;
    const int row0 = blockIdx.y * 128;
    const int col0 = blockIdx.x * 128;

    float acc[4][4][4];
#pragma unroll
    for (int i = 0; i < 4; i++)
#pragma unroll
        for (int j = 0; j < 4; j++)
#pragma unroll
            for (int e = 0; e < 4; e++) acc[i][j][e] = 0.f;

    const int ldr = tid >> 3;           // 0..31 row slice
    const int ldc = (tid & 7) << 2;     // float col 0..28
    const int lcp = (tid & 7) << 1;     // packed col 0..14

    // ldmatrix per-lane address components
    const int a_row = ((lane >> 3) & 1) * 8 + (lane & 7);  // + mw + i*16
    const int a_col = (lane >> 4) * 4;                     // + ks*8
    const int b_row = (lane >> 4) * 8 + (lane & 7);        // + nw + jp*16
    const int b_col = ((lane >> 3) & 1) * 4;               // + ks*8

    float4 pa[4], pb[4];
#pragma unroll
    for (int it = 0; it < 4; it++) {
        const int r = ldr + it * 32;
        pa[it] = *(const float4*)(A  + (size_t)(row0 + r) * K + ldc);
        pb[it] = *(const float4*)(Bw + (size_t)(col0 + r) * K + ldc);
    }
    {
        uint32_t* A0 = smu;            uint32_t* A1 = A0 + PTILE;
        uint32_t* B0 = A1 + PTILE;     uint32_t* B1 = B0 + PTILE;
#pragma unroll
        for (int it = 0; it < 4; it++) {
            const int r = ldr + it * 32;
            uint32_t h0, l0, h1, l1;
            split2bf(pa[it].x, pa[it].y, h0, l0);
            split2bf(pa[it].z, pa[it].w, h1, l1);
            *(uint2*)(A0 + r * PS + lcp) = make_uint2(h0, h1);
            *(uint2*)(A1 + r * PS + lcp) = make_uint2(l0, l1);
            split2bf(pb[it].x, pb[it].y, h0, l0);
            split2bf(pb[it].z, pb[it].w, h1, l1);
            *(uint2*)(B0 + r * PS + lcp) = make_uint2(h0, h1);
            *(uint2*)(B1 + r * PS + lcp) = make_uint2(l0, l1);
        }
    }
    const int KCH = K >> 5;
    if (KCH > 1) {
#pragma unroll
        for (int it = 0; it < 4; it++) {
            const int r = ldr + it * 32;
            pa[it] = *(const float4*)(A  + (size_t)(row0 + r) * K + 32 + ldc);
            pb[it] = *(const float4*)(Bw + (size_t)(col0 + r) * K + 32 + ldc);
        }
    }
    __syncthreads();

    for (int kt = 0; kt < KCH; kt++) {
        const uint32_t cur = smem_base + (uint32_t)((kt & 1) * PSTAGE) * 4;
        uint32_t* nxt = smu + ((kt + 1) & 1) * PSTAGE;

        if (kt + 1 < KCH) {
            uint32_t* A0 = nxt;        uint32_t* A1 = A0 + PTILE;
            uint32_t* B0 = A1 + PTILE; uint32_t* B1 = B0 + PTILE;
#pragma unroll
            for (int it = 0; it < 4; it++) {
                const int r = ldr + it * 32;
                uint32_t h0, l0, h1, l1;
                split2bf(pa[it].x, pa[it].y, h0, l0);
                split2bf(pa[it].z, pa[it].w, h1, l1);
                *(uint2*)(A0 + r * PS + lcp) = make_uint2(h0, h1);
                *(uint2*)(A1 + r * PS + lcp) = make_uint2(l0, l1);
                split2bf(pb[it].x, pb[it].y, h0, l0);
                split2bf(pb[it].z, pb[it].w, h1, l1);
                *(uint2*)(B0 + r * PS + lcp) = make_uint2(h0, h1);
                *(uint2*)(B1 + r * PS + lcp) = make_uint2(l0, l1);
            }
        }
        if (kt + 2 < KCH) {
            const int k0n = (kt + 2) << 5;
#pragma unroll
            for (int it = 0; it < 4; it++) {
                const int r = ldr + it * 32;
                pa[it] = *(const float4*)(A  + (size_t)(row0 + r) * K + k0n + ldc);
                pb[it] = *(const float4*)(Bw + (size_t)(col0 + r) * K + k0n + ldc);
            }
        }

        {
            const uint32_t A0a = cur;
            const uint32_t A1a = cur + PTILE * 4;
            const uint32_t B0a = cur + 2 * PTILE * 4;
            const uint32_t B1a = cur + 3 * PTILE * 4;
#pragma unroll
            for (int ks = 0; ks < 2; ks++) {
                uint32_t afh[4][4], afl[4][4], bf[2][4], bl2[2][4];
#pragma unroll
                for (int i = 0; i < 4; i++) {
                    const uint32_t off =
                        (uint32_t)(((mw + i * 16 + a_row) * PS) + ks * 8 + a_col) * 4;
                    ldsm4(afh[i], A0a + off);
                    ldsm4(afl[i], A1a + off);
                }
#pragma unroll
                for (int jp = 0; jp < 2; jp++) {
                    const uint32_t off =
                        (uint32_t)(((nw + jp * 16 + b_row) * PS) + ks * 8 + b_col) * 4;
                    ldsm4(bf[jp],  B0a + off);
                    ldsm4(bl2[jp], B1a + off);
                }
#pragma unroll
                for (int i = 0; i < 4; i++)
#pragma unroll
                    for (int j = 0; j < 4; j++) {
                        const uint32_t* bh = &bf[j >> 1][(j & 1) * 2];
                        const uint32_t* bl = &bl2[j >> 1][(j & 1) * 2];
                        mma_bf16(acc[i][j], afh[i], bh);
                        mma_bf16(acc[i][j], afh[i], bl);
                        mma_bf16(acc[i][j], afl[i], bh);
                    }
            }
        }
        __syncthreads();
    }

#pragma unroll
    for (int i = 0; i < 4; i++) {
        const int r = row0 + mw + i * 16 + gid;
#pragma unroll
        for (int j = 0; j < 4; j++) {
            const int ccol = col0 + nw + j * 8 + tig * 2;
            float2 v0, v1;
            v0.x = acc[i][j][0] + bias[ccol];
            v0.y = acc[i][j][1] + bias[ccol + 1];
            v1.x = acc[i][j][2] + bias[ccol];
            v1.y = acc[i][j][3] + bias[ccol + 1];
            *(float2*)(C + (size_t)r * N + ccol)       = v0;
            *(float2*)(C + (size_t)(r + 8) * N + ccol) = v1;
        }
    }
}

// ===========================================================================
// bf16x2 tensor-core flash attention, ldmatrix for K and P fragments.
// Block = 128 threads / 4 warps; one (64-row q tile, b, h).
// ===========================================================================
#define KS_ 36
#define VS_ 72
#define K_TILE (64 * KS_)     // 2304 u32
#define V_TILE (32 * VS_)     // 2304 u32
#define ATT_SMEM_BYTES ((4 * K_TILE + 2 * V_TILE) * 4)   // 55296 B

__global__ __launch_bounds__(128, 2) void flash_attn_tc(
    const float* __restrict__ qkv, const int* __restrict__ causal_flag,
    float* __restrict__ av)
{
    extern __shared__ uint32_t smu[];
    uint32_t* K0 = smu;
    uint32_t* K1 = K0 + K_TILE;
    uint32_t* P0 = K1 + K_TILE;
    uint32_t* P1 = P0 + K_TILE;
    uint32_t* V0 = P1 + K_TILE;
    uint32_t* V1 = V0 + V_TILE;
    const uint32_t smem_base = (uint32_t)__cvta_generic_to_shared(smu);
    const uint32_t K0a = smem_base;
    const uint32_t K1a = smem_base + (uint32_t)K_TILE * 4;
    const uint32_t P0a = smem_base + (uint32_t)(2 * K_TILE) * 4;
    const uint32_t P1a = smem_base + (uint32_t)(3 * K_TILE) * 4;

    const int tid  = threadIdx.x;
    const int wid  = tid >> 5;
    const int lane = tid & 31;
    const int gid  = lane >> 2;
    const int tig  = lane & 3;
    const int qt   = blockIdx.x;
    const int b    = blockIdx.y >> 4;
    const int h    = blockIdx.y & 15;
    const int is_causal = *causal_flag;

    // K loader slots
    const int klr = tid >> 4;            // base row 0..7
    const int kd4 = (tid & 15) << 2;     // float col
    const int kcp = (tid & 15) << 1;     // packed col
    // V loader slots
    const int vsp = tid >> 5;            // base packed row 0..3
    const int vd2 = (lane) << 1;         // uint32 col 0..62

    // ldmatrix per-lane address components
    const int kb_row = (lane >> 4) * 8 + (lane & 7);       // + jp*16
    const int kb_col = ((lane >> 3) & 1) * 4;              // + ks*8
    const int pa_row = wid * 16 + ((lane >> 3) & 1) * 8 + (lane & 7);
    const int pa_col = (lane >> 4) * 4;                    // + ks*8

    // ---- Q fragments (bf16 hi/lo, packed) ----
    uint32_t qp0[4][4], qp1[4][4];
    {
        const int r0 = qt * 64 + wid * 16 + gid;
        const float* q0 = qkv + ((size_t)(r0 * BATCH + b)) * QKV_N + h * DH;
        const float* q8 = q0 + (size_t)8 * BATCH * QKV_N;
#pragma unroll
        for (int ks = 0; ks < 4; ks++) {
            const float2 qa = *(const float2*)(q0 + ks * 16 + tig * 2);
            const float2 qb = *(const float2*)(q8 + ks * 16 + tig * 2);
            const float2 qc = *(const float2*)(q0 + ks * 16 + tig * 2 + 8);
            const float2 qd = *(const float2*)(q8 + ks * 16 + tig * 2 + 8);
            split2bf(qa.x, qa.y, qp0[ks][0], qp1[ks][0]);
            split2bf(qb.x, qb.y, qp0[ks][1], qp1[ks][1]);
            split2bf(qc.x, qc.y, qp0[ks][2], qp1[ks][2]);
            split2bf(qd.x, qd.y, qp0[ks][3], qp1[ks][3]);
        }
    }

    // Prologue: prefetch K and V for kt = 0.
    float4 kreg[8];
    float2 vra[8], vrb[8];
#pragma unroll
    for (int it = 0; it < 8; it++) {
        const int kr = klr + it * 8;
        kreg[it] = *(const float4*)(
            qkv + ((size_t)(kr * BATCH + b)) * QKV_N + h * DH + kd4 + DM);
        const int sp = vsp + it * 4;
        const float* vb0 =
            qkv + ((size_t)((2 * sp) * BATCH + b)) * QKV_N + h * DH + vd2 + 2 * DM;
        vra[it] = *(const float2*)(vb0);
        vrb[it] = *(const float2*)(vb0 + (size_t)BATCH * QKV_N);
    }

    float o[8][4];
#pragma unroll
    for (int j = 0; j < 8; j++)
#pragma unroll
        for (int e = 0; e < 4; e++) o[j][e] = 0.f;
    float m0 = -1e30f, m1 = -1e30f, l0 = 0.f, l1 = 0.f;

    const int kt_end = is_causal ? qt : (SEQ / 64 - 1);

    for (int kt = 0; kt <= kt_end; kt++) {
        __syncthreads();
        // ---- store prefetched K (packed along d) and V (packed along s) ----
#pragma unroll
        for (int it = 0; it < 8; it++) {
            const int kr = klr + it * 8;
            uint32_t h0, l0_, h1, l1_;
            split2bf(kreg[it].x, kreg[it].y, h0, l0_);
            split2bf(kreg[it].z, kreg[it].w, h1, l1_);
            *(uint2*)(K0 + kr * KS_ + kcp) = make_uint2(h0, h1);
            *(uint2*)(K1 + kr * KS_ + kcp) = make_uint2(l0_, l1_);
            const int sp = vsp + it * 4;
            split2bf(vra[it].x, vrb[it].x, h0, l0_);
            split2bf(vra[it].y, vrb[it].y, h1, l1_);
            *(uint2*)(V0 + sp * VS_ + vd2) = make_uint2(h0, h1);
            *(uint2*)(V1 + sp * VS_ + vd2) = make_uint2(l0_, l1_);
        }
        __syncthreads();

        // Prefetch next K tile (retires under QK MMAs).
        if (kt < kt_end) {
#pragma unroll
            for (int it = 0; it < 8; it++) {
                const int kr = (kt + 1) * 64 + klr + it * 8;
                kreg[it] = *(const float4*)(
                    qkv + ((size_t)(kr * BATCH + b)) * QKV_N + h * DH + kd4 + DM);
            }
        }

        // ---- S = Q K^T (3-product bf16x2, ldmatrix K fragments) ----
        float s[8][4];
#pragma unroll
        for (int j = 0; j < 8; j++)
#pragma unroll
            for (int e = 0; e < 4; e++) s[j][e] = 0.f;

#pragma unroll
        for (int ks = 0; ks < 4; ks++) {
            uint32_t kf[4][4], kl[4][4];
#pragma unroll
            for (int jp = 0; jp < 4; jp++) {
                const uint32_t off =
                    (uint32_t)(((jp * 16 + kb_row) * KS_) + ks * 8 + kb_col) * 4;
                ldsm4(kf[jp], K0a + off);
                ldsm4(kl[jp], K1a + off);
            }
#pragma unroll
            for (int j = 0; j < 8; j++) {
                const uint32_t* bh = &kf[j >> 1][(j & 1) * 2];
                const uint32_t* bl = &kl[j >> 1][(j & 1) * 2];
                mma_bf16(s[j], qp0[ks], bh);
                mma_bf16(s[j], qp0[ks], bl);
                mma_bf16(s[j], qp1[ks], bh);
            }
        }

        // ---- scale x8, causal mask ----
#pragma unroll
        for (int j = 0; j < 8; j++)
#pragma unroll
            for (int e = 0; e < 4; e++) s[j][e] *= 8.0f;

        if (is_causal && kt == qt) {
            const int r0 = wid * 16 + gid;
#pragma unroll
            for (int j = 0; j < 8; j++) {
                const int c = j * 8 + tig * 2;
                if (c     > r0)     s[j][0] = -1e30f;
                if (c + 1 > r0)     s[j][1] = -1e30f;
                if (c     > r0 + 8) s[j][2] = -1e30f;
                if (c + 1 > r0 + 8) s[j][3] = -1e30f;
            }
        }

        // ---- online softmax ----
        float rm0 = -1e30f, rm1 = -1e30f;
#pragma unroll
        for (int j = 0; j < 8; j++) {
            rm0 = fmaxf(rm0, fmaxf(s[j][0], s[j][1]));
            rm1 = fmaxf(rm1, fmaxf(s[j][2], s[j][3]));
        }
        rm0 = fmaxf(rm0, __shfl_xor_sync(0xffffffffu, rm0, 1));
        rm0 = fmaxf(rm0, __shfl_xor_sync(0xffffffffu, rm0, 2));
        rm1 = fmaxf(rm1, __shfl_xor_sync(0xffffffffu, rm1, 1));
        rm1 = fmaxf(rm1, __shfl_xor_sync(0xffffffffu, rm1, 2));

        const float mn0 = fmaxf(m0, rm0);
        const float mn1 = fmaxf(m1, rm1);
        const float corr0 = __expf(m0 - mn0);
        const float corr1 = __expf(m1 - mn1);

        float rs0 = 0.f, rs1 = 0.f;
        const int prow = wid * 16 + gid;
#pragma unroll
        for (int j = 0; j < 8; j++) {
            const float p00 = __expf(s[j][0] - mn0);
            const float p01 = __expf(s[j][1] - mn0);
            const float p10 = __expf(s[j][2] - mn1);
            const float p11 = __expf(s[j][3] - mn1);
            rs0 += p00 + p01;
            rs1 += p10 + p11;
            uint32_t hh, ll;
            split2bf(p00, p01, hh, ll);
            P0[prow * KS_ + j * 4 + tig] = hh;
            P1[prow * KS_ + j * 4 + tig] = ll;
            split2bf(p10, p11, hh, ll);
            P0[(prow + 8) * KS_ + j * 4 + tig] = hh;
            P1[(prow + 8) * KS_ + j * 4 + tig] = ll;
        }
        rs0 += __shfl_xor_sync(0xffffffffu, rs0, 1);
        rs0 += __shfl_xor_sync(0xffffffffu, rs0, 2);
        rs1 += __shfl_xor_sync(0xffffffffu, rs1, 1);
        rs1 += __shfl_xor_sync(0xffffffffu, rs1, 2);

        l0 = l0 * corr0 + rs0;
        l1 = l1 * corr1 + rs1;
        m0 = mn0;
        m1 = mn1;

#pragma unroll
        for (int j = 0; j < 8; j++) {
            o[j][0] *= corr0; o[j][1] *= corr0;
            o[j][2] *= corr1; o[j][3] *= corr1;
        }

        // Prefetch next V tile (retires under PV MMAs).
        if (kt < kt_end) {
#pragma unroll
            for (int it = 0; it < 8; it++) {
                const int sp = vsp + it * 4;
                const float* vb0 = qkv +
                    ((size_t)(((kt + 1) * 64 + 2 * sp) * BATCH + b)) * QKV_N +
                    h * DH + vd2 + 2 * DM;
                vra[it] = *(const float2*)(vb0);
                vrb[it] = *(const float2*)(vb0 + (size_t)BATCH * QKV_N);
            }
        }

        __syncwarp();   // P rows for this warp written only by this warp

        // ---- O += P @ V (3-product bf16x2, ldmatrix P fragments) ----
#pragma unroll
        for (int ks = 0; ks < 4; ks++) {
            const int c0 = ks * 8 + tig;
            const int c1 = c0 + 4;
            uint32_t ah[4], al[4];
            {
                const uint32_t off =
                    (uint32_t)((pa_row * KS_) + ks * 8 + pa_col) * 4;
                ldsm4(ah, P0a + off);
                ldsm4(al, P1a + off);
            }
#pragma unroll
            for (int j = 0; j < 8; j++) {
                const int n = j * 8 + gid;
                uint32_t bh[2], bl[2];
                bh[0] = V0[(c0) * VS_ + n];
                bh[1] = V0[(c1) * VS_ + n];
                bl[0] = V1[(c0) * VS_ + n];
                bl[1] = V1[(c1) * VS_ + n];
                mma_bf16(o[j], ah, bh);
                mma_bf16(o[j], ah, bl);
                mma_bf16(o[j], al, bh);
            }
        }
    }

    // ---- normalize + write av in (t, b, h*64+d) layout ----
    const float inv0 = 1.0f / l0;
    const float inv1 = 1.0f / l1;
    const int r0 = qt * 64 + wid * 16 + gid;
    float* dst0 = av + ((size_t)(r0 * BATCH + b)) * DM + h * DH;
    float* dst8 = dst0 + (size_t)8 * BATCH * DM;
#pragma unroll
    for (int j = 0; j < 8; j++) {
        float2 v;
        v.x = o[j][0] * inv0; v.y = o[j][1] * inv0;
        *(float2*)(dst0 + j * 8 + tig * 2) = v;
        v.x = o[j][2] * inv1; v.y = o[j][3] * inv1;
        *(float2*)(dst8 + j * 8 + tig * 2) = v;
    }
}

// ---------------------------------------------------------------------------
extern "C" void kernel_launch(void* const* d_in, const int* in_sizes, int n_in,
                              void* d_out, int out_size)
{
    const float* x         = (const float*)d_in[0];
    const float* qkv_w     = (const float*)d_in[1];
    const float* qkv_b     = (const float*)d_in[2];
    const float* out_w     = (const float*)d_in[3];
    const float* out_b     = (const float*)d_in[4];
    const int*   is_causal = (const int*)d_in[5];
    float*       out       = (float*)d_out;

    void* qkv_ptr = nullptr;
    void* av_ptr  = nullptr;
    cudaGetSymbolAddress(&qkv_ptr, g_qkv);
    cudaGetSymbolAddress(&av_ptr,  g_av);

    cudaFuncSetAttribute(gemm_bf16x2,
                         cudaFuncAttributeMaxDynamicSharedMemorySize, GEMM_SMEM);
    cudaFuncSetAttribute(flash_attn_tc,
                         cudaFuncAttributeMaxDynamicSharedMemorySize, ATT_SMEM_BYTES);

    // QKV projection: (4096,1024) @ (3072,1024)^T -> (4096,3072)
    {
        dim3 grid(QKV_N / 128, MROWS / 128);
        gemm_bf16x2<<<grid, 256, GEMM_SMEM>>>(x, qkv_w, qkv_b, (float*)qkv_ptr,
                                              MROWS, QKV_N, DM);
    }

    // Attention (bf16x2 tensor-core flash)
    {
        dim3 grid(SEQ / 64, BATCH * NH);
        flash_attn_tc<<<grid, 128, ATT_SMEM_BYTES>>>(
            (const float*)qkv_ptr, is_causal, (float*)av_ptr);
    }

    // Output projection: (4096,1024) @ (1024,1024)^T -> (4096,1024)
    {
        dim3 grid(DM / 128, MROWS / 128);
        gemm_bf16x2<<<grid, 256, GEMM_SMEM>>>((const float*)av_ptr, out_w, out_b, out,
                                              MROWS, DM, DM);
    }
}